// round 2
// baseline (speedup 1.0000x reference)
#include <cuda_runtime.h>
#include <math.h>

#define B_SZ     256
#define S_LEN    1024
#define T_LEN    21
#define NFREQ    11
#define NCH      32
#define COUT     64
#define POOL_T   512
#define HID      32
#define NWROWS   46
#define ROWP     264
#define TS       256

/* ---------------- device scratch (module-static, no runtime alloc) ------ */
__device__ __align__(16) float g_tw[T_LEN * NFREQ * 2];
__device__ __align__(16) float g_L[NWROWS * T_LEN];
__device__ __align__(16) float g_weff[NCH * COUT * 4];
__device__ __align__(16) float g_feat[B_SZ * NCH * S_LEN];
__device__ __align__(16) float g_pooled[B_SZ * POOL_T * COUT];
__device__ __align__(16) float g_xg[B_SZ * POOL_T * 128];   /* gates pre-act */

__constant__ float c_lo[8] = {
    -0.010597401784997278f,  0.032883011666982945f,  0.030841381835986965f,
    -0.18703481171888114f,  -0.02798376941698385f,   0.6308807679295904f,
     0.7148465705525415f,    0.23037781330885523f };
__constant__ float c_hi[8] = {
    -0.23037781330885523f,   0.7148465705525415f,   -0.6308807679295904f,
    -0.02798376941698385f,   0.18703481171888114f,   0.030841381835986965f,
    -0.032883011666982945f, -0.010597401784997278f };

/* ---------------- packed f32x2 helpers (sm_100+) ------------------------ */
static __device__ __forceinline__ unsigned long long pk2(float a, float b) {
    unsigned long long r;
    asm("mov.b64 %0,{%1,%2};" : "=l"(r) : "f"(a), "f"(b));
    return r;
}
static __device__ __forceinline__ void upk2(unsigned long long v, float& a, float& b) {
    asm("mov.b64 {%0,%1},%2;" : "=f"(a), "=f"(b) : "l"(v));
}
static __device__ __forceinline__ void ffma2(unsigned long long& d,
                                             unsigned long long a,
                                             unsigned long long b) {
    asm("fma.rn.f32x2 %0,%1,%2,%0;" : "+l"(d) : "l"(a), "l"(b));
}
static __device__ __forceinline__ void fadd2(unsigned long long& d,
                                             unsigned long long a) {
    asm("add.rn.f32x2 %0,%0,%1;" : "+l"(d) : "l"(a));
}

/* ============ K0: twiddles, wavelet map L, folded conv weights =========== */
__global__ void precompute_kernel(const float* __restrict__ conv_w)
{
    int tid = threadIdx.x;

    for (int i = tid; i < T_LEN * NFREQ; i += blockDim.x) {
        int n = i / NFREQ, k = i % NFREQ;
        double ang = 2.0 * (double)(k * n) / 21.0;
        g_tw[2 * i]     = (float)cospi(ang);
        g_tw[2 * i + 1] = (float)(-sinpi(ang));
    }

    if (tid < T_LEN) {
        float a[21];
        #pragma unroll
        for (int i = 0; i < 21; i++) a[i] = (i == tid) ? 1.f : 0.f;
        int n = 21;
        const int rowbase[4] = {32, 22, 14, 7};
        for (int lev = 0; lev < 4; lev++) {
            int mout = (n + 5) / 2 + 1;
            float cA[14];
            for (int m = 0; m < mout; m++) {
                float aL = 0.f, aH = 0.f;
                #pragma unroll
                for (int j = 0; j < 8; j++) {
                    int idx = 2 * m + 1 - j;
                    if (idx < 0)  idx = -idx - 1;
                    if (idx >= n) idx = 2 * n - 1 - idx;
                    aL += c_lo[j] * a[idx];
                    aH += c_hi[j] * a[idx];
                }
                cA[m] = aL;
                g_L[(rowbase[lev] + m) * T_LEN + tid] = aH;
            }
            for (int m = 0; m < mout; m++) a[m] = cA[m];
            n = mout;
        }
        for (int m = 0; m < n; m++)
            g_L[m * T_LEN + tid] = a[m];
    }
    __syncthreads();

    for (int idx = tid; idx < COUT * NCH; idx += blockDim.x) {
        int c  = idx / NCH;
        int ci = idx % NCH;
        for (int k = 0; k < 3; k++) {
            float val = conv_w[(c * 78 + ci) * 3 + k];
            if (ci < T_LEN) {
                for (int j = 0; j < NWROWS; j++)
                    val += conv_w[(c * 78 + 32 + j) * 3 + k] * g_L[j * T_LEN + ci];
            }
            g_weff[(ci * COUT + c) * 4 + k] = val;
        }
        g_weff[(ci * COUT + c) * 4 + 3] = 0.f;
    }
}

/* ============ K1: feat[b][ch][s] = [x(21), |rfft|(11)] =================== */
__global__ void __launch_bounds__(128) feat_kernel(const float* __restrict__ x)
{
    __shared__ float sx[128 * T_LEN];
    __shared__ float stw[T_LEN * NFREQ * 2];

    int b  = blockIdx.x >> 3;
    int s0 = (blockIdx.x & 7) << 7;
    int tid = threadIdx.x;

    for (int i = tid; i < 128 * T_LEN; i += 128)
        sx[i] = x[(size_t)(b * S_LEN + s0) * T_LEN + i];
    for (int i = tid; i < T_LEN * NFREQ * 2; i += 128)
        stw[i] = g_tw[i];
    __syncthreads();

    float xr[T_LEN];
    #pragma unroll
    for (int i = 0; i < T_LEN; i++) xr[i] = sx[tid * T_LEN + i];

    int s = s0 + tid;
    float* fb = g_feat + (size_t)b * NCH * S_LEN + s;
    #pragma unroll
    for (int i = 0; i < T_LEN; i++) fb[i * S_LEN] = xr[i];

    for (int k = 0; k < NFREQ; k++) {
        float re = 0.f, im = 0.f;
        #pragma unroll
        for (int n = 0; n < T_LEN; n++) {
            float cw = stw[(n * NFREQ + k) * 2];
            float sw = stw[(n * NFREQ + k) * 2 + 1];
            re = fmaf(xr[n], cw, re);
            im = fmaf(xr[n], sw, im);
        }
        fb[(T_LEN + k) * S_LEN] = sqrtf(re * re + im * im);
    }
}

/* ============ K2: conv3(32->64) + ReLU + maxpool2 -> pooled[b][t][c] ===== */
__global__ void __launch_bounds__(256) conv_pool_kernel(const float* __restrict__ conv_b)
{
    extern __shared__ float sm[];
    float* sin_ = sm;
    float* sw   = sm + NCH * ROWP;

    int b  = blockIdx.x >> 2;
    int s0 = (blockIdx.x & 3) * TS;
    int tid = threadIdx.x;

    for (int i = tid; i < NCH * COUT * 4; i += 256) sw[i] = g_weff[i];

    const float* fb = g_feat + (size_t)b * NCH * S_LEN;
    for (int i = tid; i < NCH * (TS + 2); i += 256) {
        int ci = i / (TS + 2), col = i % (TS + 2);
        int s = s0 + col - 1;
        sin_[ci * ROWP + col] = (s >= 0 && s < S_LEN) ? fb[ci * S_LEN + s] : 0.f;
    }
    __syncthreads();

    int c  = tid & 63;
    int sg = tid >> 6;
    float bias = conv_b[c];
    float* pout = g_pooled + (size_t)b * POOL_T * COUT + c;

    for (int ch = 0; ch < 8; ch++) {
        int cs = sg * 64 + ch * 8;
        float acc[8];
        #pragma unroll
        for (int i = 0; i < 8; i++) acc[i] = bias;

        for (int ci = 0; ci < NCH; ci++) {
            const float4* row = (const float4*)(sin_ + ci * ROWP + cs);
            float4 v0 = row[0], v1 = row[1], v2 = row[2];
            float4 w  = *(const float4*)(sw + (ci * COUT + c) * 4);
            float v[12] = { v0.x, v0.y, v0.z, v0.w,
                            v1.x, v1.y, v1.z, v1.w,
                            v2.x, v2.y, v2.z, v2.w };
            #pragma unroll
            for (int i = 0; i < 8; i++)
                acc[i] = fmaf(w.x, v[i], fmaf(w.y, v[i + 1], fmaf(w.z, v[i + 2], acc[i])));
        }

        int t0 = (s0 + cs) >> 1;
        #pragma unroll
        for (int i = 0; i < 4; i++) {
            float a0 = fmaxf(acc[2 * i],     0.f);
            float a1 = fmaxf(acc[2 * i + 1], 0.f);
            pout[(t0 + i) * COUT] = fmaxf(a0, a1);
        }
    }
}

/* ============ K2b: xg = pooled @ w_ih^T + bias  (FFMA2 GEMM) ============= */
/* out layout per row: float4 per hidden unit j = (z_i, z_f, z_g, z_o).     */
/* pair index p: even p=2j -> gates (j, 32+j); odd p=2j+1 -> (64+j, 96+j).  */
#define GT 64   /* pooled rows per CTA */
__global__ void __launch_bounds__(128) xg_gemm_kernel(
    const float* __restrict__ w_ih, const float* __restrict__ b_ih,
    const float* __restrict__ b_hh)
{
    extern __shared__ unsigned long long sm8[];
    unsigned long long* sA = sm8;             /* [c=64][pitch 66] dup pairs */
    unsigned long long* sW = sm8 + 64 * 66;   /* [c=64][p=64] gate pairs    */

    int tid = threadIdx.x;
    int R0  = blockIdx.x * GT;

    for (int idx = tid; idx < 4096; idx += 128) {
        int c = idx & 63, p = idx >> 6;
        int j = p >> 1;
        int g0 = (p & 1) ? (64 + j) : j;
        int g1 = g0 + 32;
        sW[c * 64 + p] = pk2(w_ih[g0 * 64 + c], w_ih[g1 * 64 + c]);
    }

    const float* Ap = g_pooled + (size_t)R0 * 64;
    {
        int r0 = tid >> 4, c4 = (tid & 15) * 4;
        for (int rr = r0; rr < GT; rr += 8) {
            float4 v = *(const float4*)(Ap + rr * 64 + c4);
            sA[(c4 + 0) * 66 + rr] = pk2(v.x, v.x);
            sA[(c4 + 1) * 66 + rr] = pk2(v.y, v.y);
            sA[(c4 + 2) * 66 + rr] = pk2(v.z, v.z);
            sA[(c4 + 3) * 66 + rr] = pk2(v.w, v.w);
        }
    }
    __syncthreads();

    int tx = tid & 15, ty = tid >> 4;
    int p0 = tx * 4, t0 = ty * 8;

    unsigned long long bias[4];
    #pragma unroll
    for (int q = 0; q < 4; q++) {
        int p = p0 + q, j = p >> 1;
        int g0 = (p & 1) ? (64 + j) : j;
        int g1 = g0 + 32;
        bias[q] = pk2(b_ih[g0] + b_hh[g0], b_ih[g1] + b_hh[g1]);
    }

    unsigned long long acc[8][4];
    #pragma unroll
    for (int i = 0; i < 8; i++)
        #pragma unroll
        for (int q = 0; q < 4; q++) acc[i][q] = bias[q];

    #pragma unroll 4
    for (int k = 0; k < 64; k++) {
        const unsigned long long* ar = sA + k * 66 + t0;
        ulonglong2 a01 = *(const ulonglong2*)(ar + 0);
        ulonglong2 a23 = *(const ulonglong2*)(ar + 2);
        ulonglong2 a45 = *(const ulonglong2*)(ar + 4);
        ulonglong2 a67 = *(const ulonglong2*)(ar + 6);
        const unsigned long long* wr = sW + k * 64 + p0;
        ulonglong2 w01 = *(const ulonglong2*)(wr + 0);
        ulonglong2 w23 = *(const ulonglong2*)(wr + 2);
        unsigned long long av[8] = { a01.x, a01.y, a23.x, a23.y,
                                     a45.x, a45.y, a67.x, a67.y };
        unsigned long long wv[4] = { w01.x, w01.y, w23.x, w23.y };
        #pragma unroll
        for (int i = 0; i < 8; i++)
            #pragma unroll
            for (int q = 0; q < 4; q++)
                ffma2(acc[i][q], av[i], wv[q]);
    }

    float* outp = g_xg + (size_t)R0 * 128;
    #pragma unroll
    for (int i = 0; i < 8; i++) {
        ulonglong2 s0, s1;
        s0.x = acc[i][0]; s0.y = acc[i][1];
        s1.x = acc[i][2]; s1.y = acc[i][3];
        *(ulonglong2*)(outp + (size_t)(t0 + i) * 128 + p0 * 2)     = s0;
        *(ulonglong2*)(outp + (size_t)(t0 + i) * 128 + p0 * 2 + 4) = s1;
    }
}

/* ============ K3: LSTM recurrence, 1 warp per batch, FFMA2 =============== */
static __device__ __forceinline__ float sigf(float z) {
    return __fdividef(1.f, 1.f + __expf(-z));
}
static __device__ __forceinline__ float tanhf_(float z) {
    /* tanh(z) = 1 - 2/(exp(2z)+1); robust at +-inf */
    return fmaf(-2.f, __fdividef(1.f, __expf(2.f * z) + 1.f), 1.f);
}

__global__ void __launch_bounds__(32) lstm2_kernel(
    const float* __restrict__ w_hh, const float* __restrict__ fc_w,
    const float* __restrict__ fc_b, float* __restrict__ out)
{
    __shared__ __align__(16) float4 wst[32][32];             /* [k][j] gates */
    __shared__ __align__(16) unsigned long long s_h2[2][32]; /* dup h pairs  */

    int b = blockIdx.x;
    int lane = threadIdx.x;

    #pragma unroll
    for (int k = 0; k < 32; k++)
        wst[k][lane] = make_float4(w_hh[lane * 32 + k],
                                   w_hh[(32 + lane) * 32 + k],
                                   w_hh[(64 + lane) * 32 + k],
                                   w_hh[(96 + lane) * 32 + k]);
    s_h2[0][lane] = 0ull;

    float c = 0.f, h = 0.f;
    const ulonglong2* xgp = (const ulonglong2*)(g_xg + (size_t)b * POOL_T * 128);
    ulonglong2 pre0 = xgp[lane];
    ulonglong2 pre1 = xgp[32 + lane];
    __syncwarp();

    for (int t = 0; t < POOL_T; t++) {
        unsigned long long aif = pre0.x, ago = pre0.y;
        unsigned long long aif2 = 0ull, ago2 = 0ull;
        pre0 = pre1;
        int tn = (t + 2 < POOL_T) ? t + 2 : POOL_T - 1;
        pre1 = xgp[tn * 32 + lane];

        const int buf = t & 1;
        const ulonglong2* hp = (const ulonglong2*)s_h2[buf];
        #pragma unroll
        for (int kq = 0; kq < 16; kq++) {
            ulonglong2 h2 = hp[kq];
            ulonglong2 w0 = *(const ulonglong2*)&wst[2 * kq][lane];
            ulonglong2 w1 = *(const ulonglong2*)&wst[2 * kq + 1][lane];
            ffma2(aif,  w0.x, h2.x);
            ffma2(ago,  w0.y, h2.x);
            ffma2(aif2, w1.x, h2.y);
            ffma2(ago2, w1.y, h2.y);
        }
        fadd2(aif, aif2);
        fadd2(ago, ago2);

        float zi, zf, zg, zo;
        upk2(aif, zi, zf);
        upk2(ago, zg, zo);
        float ai = sigf(zi), af = sigf(zf);
        float ag = tanhf_(zg), ao = sigf(zo);
        c = fmaf(af, c, ai * ag);
        h = ao * tanhf_(c);

        s_h2[buf ^ 1][lane] = pk2(h, h);
        __syncwarp();
    }

    float v = fc_w[lane] * h;
    #pragma unroll
    for (int off = 16; off; off >>= 1)
        v += __shfl_down_sync(0xffffffffu, v, off);
    if (lane == 0) out[b] = v + fc_b[0];
}

/* ======================================================================== */
extern "C" void kernel_launch(void* const* d_in, const int* in_sizes, int n_in,
                              void* d_out, int out_size)
{
    const float* x      = (const float*)d_in[0];
    const float* conv_w = (const float*)d_in[1];
    const float* conv_b = (const float*)d_in[2];
    const float* w_ih   = (const float*)d_in[3];
    const float* w_hh   = (const float*)d_in[4];
    const float* b_ih   = (const float*)d_in[5];
    const float* b_hh   = (const float*)d_in[6];
    const float* fc_w   = (const float*)d_in[7];
    const float* fc_b   = (const float*)d_in[8];
    float* out = (float*)d_out;

    precompute_kernel<<<1, 256>>>(conv_w);
    feat_kernel<<<B_SZ * 8, 128>>>(x);

    size_t smem = (size_t)(NCH * ROWP + NCH * COUT * 4) * sizeof(float);
    cudaFuncSetAttribute(conv_pool_kernel,
                         cudaFuncAttributeMaxDynamicSharedMemorySize, (int)smem);
    conv_pool_kernel<<<B_SZ * 4, 256, smem>>>(conv_b);

    size_t smem_g = (size_t)(64 * 66 + 64 * 64) * sizeof(unsigned long long);
    cudaFuncSetAttribute(xg_gemm_kernel,
                         cudaFuncAttributeMaxDynamicSharedMemorySize, (int)smem_g);
    xg_gemm_kernel<<<(B_SZ * POOL_T) / GT, 128, smem_g>>>(w_ih, b_ih, b_hh);

    lstm2_kernel<<<B_SZ, 32>>>(w_hh, fc_w, fc_b, out);
}

// round 3
// speedup vs baseline: 1.0350x; 1.0350x over previous
#include <cuda_runtime.h>
#include <math.h>

#define B_SZ     256
#define S_LEN    1024
#define T_LEN    21
#define NFREQ    11
#define NCH      32
#define COUT     64
#define POOL_T   512
#define HID      32
#define NWROWS   46
#define ROWP     264
#define TS       256
#define XGT      128     /* rows per CTA in xg GEMM */

typedef unsigned long long u64t;

/* ---------------- device scratch (module-static, no runtime alloc) ------ */
__device__ __align__(16) float g_tw[T_LEN * NFREQ * 2];
__device__ __align__(16) float g_L[NWROWS * T_LEN];
__device__ __align__(16) float g_weff[NCH * COUT * 4];
__device__ __align__(16) float g_feat[B_SZ * NCH * S_LEN];
__device__ __align__(16) float g_pooled[B_SZ * POOL_T * COUT];
__device__ __align__(16) float g_xg[B_SZ * POOL_T * 128];   /* (i,f,g,o) per j */

__constant__ float c_lo[8] = {
    -0.010597401784997278f,  0.032883011666982945f,  0.030841381835986965f,
    -0.18703481171888114f,  -0.02798376941698385f,   0.6308807679295904f,
     0.7148465705525415f,    0.23037781330885523f };
__constant__ float c_hi[8] = {
    -0.23037781330885523f,   0.7148465705525415f,   -0.6308807679295904f,
    -0.02798376941698385f,   0.18703481171888114f,   0.030841381835986965f,
    -0.032883011666982945f, -0.010597401784997278f };

/* ---------------- packed f32x2 helpers ---------------------------------- */
static __device__ __forceinline__ u64t pk2(float a, float b) {
    u64t r;
    asm("mov.b64 %0,{%1,%2};" : "=l"(r) : "f"(a), "f"(b));
    return r;
}
static __device__ __forceinline__ void upk2(u64t v, float& a, float& b) {
    asm("mov.b64 {%0,%1},%2;" : "=f"(a), "=f"(b) : "l"(v));
}
static __device__ __forceinline__ void ffma2(u64t& d, u64t a, u64t b) {
    asm("fma.rn.f32x2 %0,%1,%2,%0;" : "+l"(d) : "l"(a), "l"(b));
}
static __device__ __forceinline__ void fadd2(u64t& d, u64t a) {
    asm("add.rn.f32x2 %0,%0,%1;" : "+l"(d) : "l"(a));
}

/* ============ K0: twiddles, wavelet map L, folded conv weights =========== */
__global__ void precompute_kernel(const float* __restrict__ conv_w)
{
    int tid = threadIdx.x;

    for (int i = tid; i < T_LEN * NFREQ; i += blockDim.x) {
        int n = i / NFREQ, k = i % NFREQ;
        double ang = 2.0 * (double)(k * n) / 21.0;
        g_tw[2 * i]     = (float)cospi(ang);
        g_tw[2 * i + 1] = (float)(-sinpi(ang));
    }

    if (tid < T_LEN) {
        float a[21];
        #pragma unroll
        for (int i = 0; i < 21; i++) a[i] = (i == tid) ? 1.f : 0.f;
        int n = 21;
        const int rowbase[4] = {32, 22, 14, 7};
        for (int lev = 0; lev < 4; lev++) {
            int mout = (n + 5) / 2 + 1;
            float cA[14];
            for (int m = 0; m < mout; m++) {
                float aL = 0.f, aH = 0.f;
                #pragma unroll
                for (int j = 0; j < 8; j++) {
                    int idx = 2 * m + 1 - j;
                    if (idx < 0)  idx = -idx - 1;
                    if (idx >= n) idx = 2 * n - 1 - idx;
                    aL += c_lo[j] * a[idx];
                    aH += c_hi[j] * a[idx];
                }
                cA[m] = aL;
                g_L[(rowbase[lev] + m) * T_LEN + tid] = aH;
            }
            for (int m = 0; m < mout; m++) a[m] = cA[m];
            n = mout;
        }
        for (int m = 0; m < n; m++)
            g_L[m * T_LEN + tid] = a[m];
    }
    __syncthreads();

    for (int idx = tid; idx < COUT * NCH; idx += blockDim.x) {
        int c  = idx / NCH;
        int ci = idx % NCH;
        for (int k = 0; k < 3; k++) {
            float val = conv_w[(c * 78 + ci) * 3 + k];
            if (ci < T_LEN) {
                for (int j = 0; j < NWROWS; j++)
                    val += conv_w[(c * 78 + 32 + j) * 3 + k] * g_L[j * T_LEN + ci];
            }
            g_weff[(ci * COUT + c) * 4 + k] = val;
        }
        g_weff[(ci * COUT + c) * 4 + 3] = 0.f;
    }
}

/* ============ K1: feat[b][ch][s] = [x(21), |rfft|(11)] =================== */
__global__ void __launch_bounds__(128) feat_kernel(const float* __restrict__ x)
{
    __shared__ float sx[128 * T_LEN];
    __shared__ float stw[T_LEN * NFREQ * 2];

    int b  = blockIdx.x >> 3;
    int s0 = (blockIdx.x & 7) << 7;
    int tid = threadIdx.x;

    for (int i = tid; i < 128 * T_LEN; i += 128)
        sx[i] = x[(size_t)(b * S_LEN + s0) * T_LEN + i];
    for (int i = tid; i < T_LEN * NFREQ * 2; i += 128)
        stw[i] = g_tw[i];
    __syncthreads();

    float xr[T_LEN];
    #pragma unroll
    for (int i = 0; i < T_LEN; i++) xr[i] = sx[tid * T_LEN + i];

    int s = s0 + tid;
    float* fb = g_feat + (size_t)b * NCH * S_LEN + s;
    #pragma unroll
    for (int i = 0; i < T_LEN; i++) fb[i * S_LEN] = xr[i];

    for (int k = 0; k < NFREQ; k++) {
        float re = 0.f, im = 0.f;
        #pragma unroll
        for (int n = 0; n < T_LEN; n++) {
            float cw = stw[(n * NFREQ + k) * 2];
            float sw = stw[(n * NFREQ + k) * 2 + 1];
            re = fmaf(xr[n], cw, re);
            im = fmaf(xr[n], sw, im);
        }
        fb[(T_LEN + k) * S_LEN] = sqrtf(re * re + im * im);
    }
}

/* ============ K2: conv3(32->64) + ReLU + maxpool2 -> pooled[b][t][c] ===== */
__global__ void __launch_bounds__(256) conv_pool_kernel(const float* __restrict__ conv_b)
{
    extern __shared__ float sm[];
    float* sin_ = sm;
    float* sw   = sm + NCH * ROWP;

    int b  = blockIdx.x >> 2;
    int s0 = (blockIdx.x & 3) * TS;
    int tid = threadIdx.x;

    for (int i = tid; i < NCH * COUT * 4; i += 256) sw[i] = g_weff[i];

    const float* fb = g_feat + (size_t)b * NCH * S_LEN;
    for (int i = tid; i < NCH * (TS + 2); i += 256) {
        int ci = i / (TS + 2), col = i % (TS + 2);
        int s = s0 + col - 1;
        sin_[ci * ROWP + col] = (s >= 0 && s < S_LEN) ? fb[ci * S_LEN + s] : 0.f;
    }
    __syncthreads();

    int c  = tid & 63;
    int sg = tid >> 6;
    float bias = conv_b[c];
    float* pout = g_pooled + (size_t)b * POOL_T * COUT + c;

    for (int ch = 0; ch < 8; ch++) {
        int cs = sg * 64 + ch * 8;
        float acc[8];
        #pragma unroll
        for (int i = 0; i < 8; i++) acc[i] = bias;

        for (int ci = 0; ci < NCH; ci++) {
            const float4* row = (const float4*)(sin_ + ci * ROWP + cs);
            float4 v0 = row[0], v1 = row[1], v2 = row[2];
            float4 w  = *(const float4*)(sw + (ci * COUT + c) * 4);
            float v[12] = { v0.x, v0.y, v0.z, v0.w,
                            v1.x, v1.y, v1.z, v1.w,
                            v2.x, v2.y, v2.z, v2.w };
            #pragma unroll
            for (int i = 0; i < 8; i++)
                acc[i] = fmaf(w.x, v[i], fmaf(w.y, v[i + 1], fmaf(w.z, v[i + 2], acc[i])));
        }

        int t0 = (s0 + cs) >> 1;
        #pragma unroll
        for (int i = 0; i < 4; i++) {
            float a0 = fmaxf(acc[2 * i],     0.f);
            float a1 = fmaxf(acc[2 * i + 1], 0.f);
            pout[(t0 + i) * COUT] = fmaxf(a0, a1);
        }
    }
}

/* ============ K2b: xg = pooled @ Wcol + bias  (FFMA2, clean layout) ====== */
/* Wcol[c][k], c = j*4+gate  <->  w_ih[gate*32+j][k].                        */
/* sW pairs over adjacent cols: cp even -> gates (i,f), odd -> (g,o), same j */
__global__ void __launch_bounds__(256) xg2_kernel(
    const float* __restrict__ w_ih, const float* __restrict__ b_ih,
    const float* __restrict__ b_hh)
{
    extern __shared__ u64t smw[];
    u64t*  sW = smw;                       /* [k=64][pitch 66] col-pairs */
    float* sA = (float*)(smw + 64 * 66);   /* [k=64][pitch 132] floats   */

    int tid = threadIdx.x;
    size_t R0 = (size_t)blockIdx.x * XGT;

    for (int idx = tid; idx < 64 * 64; idx += 256) {
        int k = idx >> 6, cp = idx & 63;
        int j = cp >> 1, g0 = (cp & 1) * 2;
        sW[k * 66 + cp] = pk2(w_ih[(g0 * 32 + j) * 64 + k],
                              w_ih[((g0 + 1) * 32 + j) * 64 + k]);
    }

    const float* Ap = g_pooled + R0 * 64;
    for (int idx = tid; idx < XGT * 16; idx += 256) {
        int r = idx >> 4, q = idx & 15;
        float4 v = *(const float4*)(Ap + r * 64 + q * 4);
        sA[(4 * q + 0) * 132 + r] = v.x;
        sA[(4 * q + 1) * 132 + r] = v.y;
        sA[(4 * q + 2) * 132 + r] = v.z;
        sA[(4 * q + 3) * 132 + r] = v.w;
    }
    __syncthreads();

    int tx = tid & 15, ty = tid >> 4;
    int r0 = ty * 8;

    u64t acc[8][4];
    #pragma unroll
    for (int i = 0; i < 8; i++)
        #pragma unroll
        for (int q = 0; q < 4; q++) acc[i][q] = 0ull;

    #pragma unroll 4
    for (int k = 0; k < 64; k++) {
        const float* ar = sA + k * 132 + r0;
        float4 av0 = *(const float4*)ar;
        float4 av1 = *(const float4*)(ar + 4);
        u64t ad[8] = { pk2(av0.x, av0.x), pk2(av0.y, av0.y),
                       pk2(av0.z, av0.z), pk2(av0.w, av0.w),
                       pk2(av1.x, av1.x), pk2(av1.y, av1.y),
                       pk2(av1.z, av1.z), pk2(av1.w, av1.w) };
        const u64t* wr = sW + k * 66 + tx;
        u64t wv[4] = { wr[0], wr[16], wr[32], wr[48] };
        #pragma unroll
        for (int i = 0; i < 8; i++)
            #pragma unroll
            for (int q = 0; q < 4; q++)
                ffma2(acc[i][q], ad[i], wv[q]);
    }

    float* outp = g_xg + R0 * 128;
    #pragma unroll
    for (int q = 0; q < 4; q++) {
        int cp = tx + q * 16;
        int j = cp >> 1, g0 = (cp & 1) * 2;
        int gi0 = g0 * 32 + j, gi1 = (g0 + 1) * 32 + j;
        u64t bp = pk2(b_ih[gi0] + b_hh[gi0], b_ih[gi1] + b_hh[gi1]);
        #pragma unroll
        for (int i = 0; i < 8; i++) {
            u64t s = acc[i][q];
            fadd2(s, bp);
            float lo, hi;
            upk2(s, lo, hi);
            *(float2*)(outp + (size_t)(r0 + i) * 128 + cp * 2) = make_float2(lo, hi);
        }
    }
}

/* ============ K3: LSTM, weights in registers, 4 warps = 4 batches ======== */
static __device__ __forceinline__ float sigf(float z) {
    return __fdividef(1.f, 1.f + __expf(-z));
}
static __device__ __forceinline__ float tanhf_(float z) {
    return fmaf(-2.f, __fdividef(1.f, __expf(2.f * z) + 1.f), 1.f);
}

__global__ void __launch_bounds__(128) lstm3_kernel(
    const float* __restrict__ w_hh, const float* __restrict__ fc_w,
    const float* __restrict__ fc_b, float* __restrict__ out)
{
    __shared__ __align__(16) u64t s_h2[4][2][16];

    int w = threadIdx.x >> 5;
    int j = threadIdx.x & 31;
    int b = blockIdx.x * 4 + w;

    /* w_hh rows for hidden j, gates i,f,g,o, packed as k-pairs in regs */
    u64t w2[4][16];
    #pragma unroll
    for (int g = 0; g < 4; g++) {
        const float4* row = (const float4*)(w_hh + (g * 32 + j) * 32);
        #pragma unroll
        for (int q = 0; q < 8; q++) {
            float4 v = row[q];
            w2[g][2 * q]     = pk2(v.x, v.y);
            w2[g][2 * q + 1] = pk2(v.z, v.w);
        }
    }

    s_h2[w][0][j & 15] = 0ull;
    float c = 0.f, h = 0.f;

    const ulonglong2* xgp = (const ulonglong2*)(g_xg + (size_t)b * POOL_T * 128);
    ulonglong2 pre[4];
    #pragma unroll
    for (int i = 0; i < 4; i++) pre[i] = xgp[i * 32 + j];
    __syncwarp();

    for (int t = 0; t < POOL_T; t++) {
        ulonglong2 z4 = pre[t & 3];
        int tn = t + 4;
        if (tn >= POOL_T) tn = POOL_T - 1;
        pre[t & 3] = xgp[(size_t)tn * 32 + j];

        const ulonglong2* hp = (const ulonglong2*)s_h2[w][t & 1];
        u64t a0 = 0, a1 = 0, a2 = 0, a3 = 0;
        u64t d0 = 0, d1 = 0, d2 = 0, d3 = 0;
        #pragma unroll
        for (int kq = 0; kq < 8; kq++) {
            ulonglong2 h2 = hp[kq];
            ffma2(a0, w2[0][2 * kq], h2.x);
            ffma2(a1, w2[1][2 * kq], h2.x);
            ffma2(a2, w2[2][2 * kq], h2.x);
            ffma2(a3, w2[3][2 * kq], h2.x);
            ffma2(d0, w2[0][2 * kq + 1], h2.y);
            ffma2(d1, w2[1][2 * kq + 1], h2.y);
            ffma2(d2, w2[2][2 * kq + 1], h2.y);
            ffma2(d3, w2[3][2 * kq + 1], h2.y);
        }
        fadd2(a0, d0); fadd2(a1, d1); fadd2(a2, d2); fadd2(a3, d3);

        float xi, xf, xg2, xo;
        upk2(z4.x, xi, xf);
        upk2(z4.y, xg2, xo);
        float lo, hi;
        upk2(a0, lo, hi); float zi = xi  + lo + hi;
        upk2(a1, lo, hi); float zf = xf  + lo + hi;
        upk2(a2, lo, hi); float zg = xg2 + lo + hi;
        upk2(a3, lo, hi); float zo = xo  + lo + hi;

        float ai = sigf(zi), af = sigf(zf);
        float ag = tanhf_(zg), ao = sigf(zo);
        c = fmaf(af, c, ai * ag);
        h = ao * tanhf_(c);

        float hn = __shfl_down_sync(0xffffffffu, h, 1);
        if (!(j & 1)) s_h2[w][(t & 1) ^ 1][j >> 1] = pk2(h, hn);
        __syncwarp();
    }

    float v = fc_w[j] * h;
    #pragma unroll
    for (int off = 16; off; off >>= 1)
        v += __shfl_down_sync(0xffffffffu, v, off);
    if (j == 0) out[b] = v + fc_b[0];
}

/* ======================================================================== */
extern "C" void kernel_launch(void* const* d_in, const int* in_sizes, int n_in,
                              void* d_out, int out_size)
{
    const float* x      = (const float*)d_in[0];
    const float* conv_w = (const float*)d_in[1];
    const float* conv_b = (const float*)d_in[2];
    const float* w_ih   = (const float*)d_in[3];
    const float* w_hh   = (const float*)d_in[4];
    const float* b_ih   = (const float*)d_in[5];
    const float* b_hh   = (const float*)d_in[6];
    const float* fc_w   = (const float*)d_in[7];
    const float* fc_b   = (const float*)d_in[8];
    float* out = (float*)d_out;

    precompute_kernel<<<1, 256>>>(conv_w);
    feat_kernel<<<B_SZ * 8, 128>>>(x);

    size_t smem = (size_t)(NCH * ROWP + NCH * COUT * 4) * sizeof(float);
    cudaFuncSetAttribute(conv_pool_kernel,
                         cudaFuncAttributeMaxDynamicSharedMemorySize, (int)smem);
    conv_pool_kernel<<<B_SZ * 4, 256, smem>>>(conv_b);

    size_t smem_g = (size_t)(64 * 66) * sizeof(u64t) +
                    (size_t)(64 * 132) * sizeof(float);
    cudaFuncSetAttribute(xg2_kernel,
                         cudaFuncAttributeMaxDynamicSharedMemorySize, (int)smem_g);
    xg2_kernel<<<(B_SZ * POOL_T) / XGT, 256, smem_g>>>(w_ih, b_ih, b_hh);

    lstm3_kernel<<<B_SZ / 4, 128>>>(w_hh, fc_w, fc_b, out);
}

// round 4
// speedup vs baseline: 1.1789x; 1.1391x over previous
#include <cuda_runtime.h>
#include <math.h>

#define B_SZ     256
#define S_LEN    1024
#define T_LEN    21
#define NFREQ    11
#define NCH      32
#define COUT     64
#define POOL_T   512
#define HID      32
#define NWROWS   46
#define ROWP2    264     /* conv smem row pitch in u64 */
#define XGT      128     /* rows per CTA in xg GEMM */

#define L2E   1.4426950408889634f
#define TL2E  2.8853900817779268f

typedef unsigned long long u64t;

/* ---------------- device scratch (module-static, no runtime alloc) ------ */
__device__ __align__(16) float g_tw[T_LEN * NFREQ * 2];
__device__ __align__(16) float g_L[NWROWS * T_LEN];
__device__ __align__(16) ulonglong2 g_w01[NCH * 32];   /* conv taps k0,k1 chan-pairs */
__device__ __align__(16) u64t g_w2v[NCH * 32];         /* conv tap k2 chan-pairs */
__device__ __align__(16) float g_feat[B_SZ * NCH * S_LEN];
__device__ __align__(16) float g_pooled[B_SZ * POOL_T * COUT];
__device__ __align__(16) float g_xg[B_SZ * POOL_T * 128]; /* prescaled (i,f,g,o)/j */

__constant__ float c_lo[8] = {
    -0.010597401784997278f,  0.032883011666982945f,  0.030841381835986965f,
    -0.18703481171888114f,  -0.02798376941698385f,   0.6308807679295904f,
     0.7148465705525415f,    0.23037781330885523f };
__constant__ float c_hi[8] = {
    -0.23037781330885523f,   0.7148465705525415f,   -0.6308807679295904f,
    -0.02798376941698385f,   0.18703481171888114f,   0.030841381835986965f,
    -0.032883011666982945f, -0.010597401784997278f };

/* ---------------- packed f32x2 + fast-math helpers ---------------------- */
static __device__ __forceinline__ u64t pk2(float a, float b) {
    u64t r;
    asm("mov.b64 %0,{%1,%2};" : "=l"(r) : "f"(a), "f"(b));
    return r;
}
static __device__ __forceinline__ void upk2(u64t v, float& a, float& b) {
    asm("mov.b64 {%0,%1},%2;" : "=f"(a), "=f"(b) : "l"(v));
}
static __device__ __forceinline__ void ffma2(u64t& d, u64t a, u64t b) {
    asm("fma.rn.f32x2 %0,%1,%2,%0;" : "+l"(d) : "l"(a), "l"(b));
}
static __device__ __forceinline__ void fadd2(u64t& d, u64t a) {
    asm("add.rn.f32x2 %0,%0,%1;" : "+l"(d) : "l"(a));
}
static __device__ __forceinline__ float ex2f(float x) {
    float r; asm("ex2.approx.f32 %0,%1;" : "=f"(r) : "f"(x)); return r;
}
static __device__ __forceinline__ float rcpf(float x) {
    float r; asm("rcp.approx.f32 %0,%1;" : "=f"(r) : "f"(x)); return r;
}
/* z prescaled by L2E:  sigmoid(z) = 1/(1+2^-z') */
static __device__ __forceinline__ float sig_p(float zp) {
    return rcpf(1.f + ex2f(-zp));
}
/* z prescaled by 2*L2E: tanh(z) = 2/(1+2^-z') - 1 */
static __device__ __forceinline__ float tanh_p(float zp) {
    return fmaf(2.f, rcpf(1.f + ex2f(-zp)), -1.f);
}

/* ============ K0: twiddles, wavelet map L, paired conv weights =========== */
__global__ void precompute_kernel(const float* __restrict__ conv_w)
{
    int tid = threadIdx.x;

    for (int i = tid; i < T_LEN * NFREQ; i += blockDim.x) {
        int n = i / NFREQ, k = i % NFREQ;
        double ang = 2.0 * (double)(k * n) / 21.0;
        g_tw[2 * i]     = (float)cospi(ang);
        g_tw[2 * i + 1] = (float)(-sinpi(ang));
    }

    if (tid < T_LEN) {
        float a[21];
        #pragma unroll
        for (int i = 0; i < 21; i++) a[i] = (i == tid) ? 1.f : 0.f;
        int n = 21;
        const int rowbase[4] = {32, 22, 14, 7};
        for (int lev = 0; lev < 4; lev++) {
            int mout = (n + 5) / 2 + 1;
            float cA[14];
            for (int m = 0; m < mout; m++) {
                float aL = 0.f, aH = 0.f;
                #pragma unroll
                for (int j = 0; j < 8; j++) {
                    int idx = 2 * m + 1 - j;
                    if (idx < 0)  idx = -idx - 1;
                    if (idx >= n) idx = 2 * n - 1 - idx;
                    aL += c_lo[j] * a[idx];
                    aH += c_hi[j] * a[idx];
                }
                cA[m] = aL;
                g_L[(rowbase[lev] + m) * T_LEN + tid] = aH;
            }
            for (int m = 0; m < mout; m++) a[m] = cA[m];
            n = mout;
        }
        for (int m = 0; m < n; m++)
            g_L[m * T_LEN + tid] = a[m];
    }
    __syncthreads();

    /* folded conv weights, channel-paired (cp, cp+32), taps k0..k2 */
    for (int idx = tid; idx < NCH * 32; idx += blockDim.x) {
        int ci = idx >> 5, cp = idx & 31;
        float vlo[3], vhi[3];
        #pragma unroll
        for (int k = 0; k < 3; k++) {
            float a = conv_w[(cp * 78 + ci) * 3 + k];
            float b = conv_w[((cp + 32) * 78 + ci) * 3 + k];
            if (ci < T_LEN) {
                for (int j = 0; j < NWROWS; j++) {
                    float l = g_L[j * T_LEN + ci];
                    a += conv_w[(cp * 78 + 32 + j) * 3 + k] * l;
                    b += conv_w[((cp + 32) * 78 + 32 + j) * 3 + k] * l;
                }
            }
            vlo[k] = a; vhi[k] = b;
        }
        ulonglong2 w01;
        w01.x = pk2(vlo[0], vhi[0]);
        w01.y = pk2(vlo[1], vhi[1]);
        g_w01[idx] = w01;
        g_w2v[idx] = pk2(vlo[2], vhi[2]);
    }
}

/* ============ K1: feat[b][ch][s] = [x(21), |rfft|(11)] =================== */
__global__ void __launch_bounds__(128) feat_kernel(const float* __restrict__ x)
{
    __shared__ float sx[128 * T_LEN];
    __shared__ float stw[T_LEN * NFREQ * 2];

    int b  = blockIdx.x >> 3;
    int s0 = (blockIdx.x & 7) << 7;
    int tid = threadIdx.x;

    for (int i = tid; i < 128 * T_LEN; i += 128)
        sx[i] = x[(size_t)(b * S_LEN + s0) * T_LEN + i];
    for (int i = tid; i < T_LEN * NFREQ * 2; i += 128)
        stw[i] = g_tw[i];
    __syncthreads();

    float xr[T_LEN];
    #pragma unroll
    for (int i = 0; i < T_LEN; i++) xr[i] = sx[tid * T_LEN + i];

    int s = s0 + tid;
    float* fb = g_feat + (size_t)b * NCH * S_LEN + s;
    #pragma unroll
    for (int i = 0; i < T_LEN; i++) fb[i * S_LEN] = xr[i];

    for (int k = 0; k < NFREQ; k++) {
        float re = 0.f, im = 0.f;
        #pragma unroll
        for (int n = 0; n < T_LEN; n++) {
            float cw = stw[(n * NFREQ + k) * 2];
            float sw = stw[(n * NFREQ + k) * 2 + 1];
            re = fmaf(xr[n], cw, re);
            im = fmaf(xr[n], sw, im);
        }
        fb[(T_LEN + k) * S_LEN] = sqrtf(re * re + im * im);
    }
}

/* ============ K2: conv3 + ReLU + maxpool2, FFMA2 channel pairs =========== */
__global__ void __launch_bounds__(512) conv_pool2_kernel(const float* __restrict__ conv_b)
{
    extern __shared__ u64t sm2[];
    u64t*       sdup = sm2;                        /* [32][ROWP2] dup pairs */
    ulonglong2* sw01 = (ulonglong2*)(sm2 + NCH * ROWP2);
    u64t*       sw2v = (u64t*)(sw01 + NCH * 32);

    int tid = threadIdx.x;
    int b   = blockIdx.x >> 2;
    int s0  = (blockIdx.x & 3) * 256;
    int cp  = tid & 31;
    int sg  = tid >> 5;            /* 0..15 */
    int cs  = sg * 16;

    const float* fb = g_feat + (size_t)b * NCH * S_LEN;
    for (int i = tid; i < NCH * 258; i += 512) {
        int ci = i / 258, col = i % 258;
        int s = s0 + col - 1;
        float v = (s >= 0 && s < S_LEN) ? fb[ci * S_LEN + s] : 0.f;
        sdup[ci * ROWP2 + col] = pk2(v, v);
    }
    for (int i = tid; i < NCH * 32; i += 512) {
        sw01[i] = g_w01[i];
        sw2v[i] = g_w2v[i];
    }
    __syncthreads();

    u64t bias2 = pk2(conv_b[cp], conv_b[cp + 32]);
    u64t acc[16];
    #pragma unroll
    for (int i = 0; i < 16; i++) acc[i] = bias2;

    for (int ci = 0; ci < NCH; ci++) {
        const ulonglong2* vp = (const ulonglong2*)(sdup + ci * ROWP2 + cs);
        ulonglong2 w01 = sw01[ci * 32 + cp];
        u64t       wk2 = sw2v[ci * 32 + cp];
        u64t v[18];
        #pragma unroll
        for (int q = 0; q < 9; q++) {
            ulonglong2 t2 = vp[q];
            v[2 * q] = t2.x; v[2 * q + 1] = t2.y;
        }
        #pragma unroll
        for (int i = 0; i < 16; i++) {
            ffma2(acc[i], w01.x, v[i]);
            ffma2(acc[i], w01.y, v[i + 1]);
            ffma2(acc[i], wk2,   v[i + 2]);
        }
    }

    float* pout = g_pooled + (size_t)b * POOL_T * COUT;
    int t0 = (s0 + cs) >> 1;
    #pragma unroll
    for (int i = 0; i < 8; i++) {
        float l0, h0, l1, h1;
        upk2(acc[2 * i],     l0, h0);
        upk2(acc[2 * i + 1], l1, h1);
        pout[(t0 + i) * COUT + cp]      = fmaxf(fmaxf(l0, l1), 0.f);
        pout[(t0 + i) * COUT + cp + 32] = fmaxf(fmaxf(h0, h1), 0.f);
    }
}

/* ============ K2b: xg = pooled @ Wcol + bias, gate-prescaled ============= */
__global__ void __launch_bounds__(256) xg2_kernel(
    const float* __restrict__ w_ih, const float* __restrict__ b_ih,
    const float* __restrict__ b_hh)
{
    extern __shared__ u64t smw[];
    u64t*  sW = smw;                       /* [k=64][pitch 66] col-pairs */
    float* sA = (float*)(smw + 64 * 66);   /* [k=64][pitch 132] floats   */

    int tid = threadIdx.x;
    size_t R0 = (size_t)blockIdx.x * XGT;

    for (int idx = tid; idx < 64 * 64; idx += 256) {
        int k = idx >> 6, cp = idx & 63;
        int j = cp >> 1, g0 = (cp & 1) * 2;
        float s0f = (cp & 1) ? TL2E : L2E;   /* i or g */
        sW[k * 66 + cp] = pk2(w_ih[(g0 * 32 + j) * 64 + k] * s0f,
                              w_ih[((g0 + 1) * 32 + j) * 64 + k] * L2E);
    }

    const float* Ap = g_pooled + R0 * 64;
    for (int idx = tid; idx < XGT * 16; idx += 256) {
        int r = idx >> 4, q = idx & 15;
        float4 v = *(const float4*)(Ap + r * 64 + q * 4);
        sA[(4 * q + 0) * 132 + r] = v.x;
        sA[(4 * q + 1) * 132 + r] = v.y;
        sA[(4 * q + 2) * 132 + r] = v.z;
        sA[(4 * q + 3) * 132 + r] = v.w;
    }
    __syncthreads();

    int tx = tid & 15, ty = tid >> 4;
    int r0 = ty * 8;

    u64t acc[8][4];
    #pragma unroll
    for (int i = 0; i < 8; i++)
        #pragma unroll
        for (int q = 0; q < 4; q++) acc[i][q] = 0ull;

    #pragma unroll 4
    for (int k = 0; k < 64; k++) {
        const float* ar = sA + k * 132 + r0;
        float4 av0 = *(const float4*)ar;
        float4 av1 = *(const float4*)(ar + 4);
        u64t ad[8] = { pk2(av0.x, av0.x), pk2(av0.y, av0.y),
                       pk2(av0.z, av0.z), pk2(av0.w, av0.w),
                       pk2(av1.x, av1.x), pk2(av1.y, av1.y),
                       pk2(av1.z, av1.z), pk2(av1.w, av1.w) };
        const u64t* wr = sW + k * 66 + tx;
        u64t wv[4] = { wr[0], wr[16], wr[32], wr[48] };
        #pragma unroll
        for (int i = 0; i < 8; i++)
            #pragma unroll
            for (int q = 0; q < 4; q++)
                ffma2(acc[i][q], ad[i], wv[q]);
    }

    float* outp = g_xg + R0 * 128;
    #pragma unroll
    for (int q = 0; q < 4; q++) {
        int cp = tx + q * 16;
        int j = cp >> 1, g0 = (cp & 1) * 2;
        int gi0 = g0 * 32 + j, gi1 = (g0 + 1) * 32 + j;
        float s0f = (cp & 1) ? TL2E : L2E;
        u64t bp = pk2((b_ih[gi0] + b_hh[gi0]) * s0f,
                      (b_ih[gi1] + b_hh[gi1]) * L2E);
        #pragma unroll
        for (int i = 0; i < 8; i++) {
            u64t s = acc[i][q];
            fadd2(s, bp);
            float lo, hi;
            upk2(s, lo, hi);
            *(float2*)(outp + (size_t)(r0 + i) * 128 + cp * 2) = make_float2(lo, hi);
        }
    }
}

/* ============ K3: LSTM, reg weights, static unroll-4 prefetch ============ */
__global__ void __launch_bounds__(256) lstm4_kernel(
    const float* __restrict__ w_hh, const float* __restrict__ fc_w,
    const float* __restrict__ fc_b, float* __restrict__ out)
{
    __shared__ __align__(16) u64t s_h2[8][2][16];

    int w = threadIdx.x >> 5;          /* 0..7: warp = batch */
    int j = threadIdx.x & 31;
    int b = blockIdx.x * 8 + w;

    const float sc[4] = { L2E, L2E, TL2E, L2E };
    u64t w2[4][16];
    #pragma unroll
    for (int g = 0; g < 4; g++) {
        const float4* row = (const float4*)(w_hh + (g * 32 + j) * 32);
        #pragma unroll
        for (int q = 0; q < 8; q++) {
            float4 v = row[q];
            w2[g][2 * q]     = pk2(v.x * sc[g], v.y * sc[g]);
            w2[g][2 * q + 1] = pk2(v.z * sc[g], v.w * sc[g]);
        }
    }

    if (j < 16) s_h2[w][0][j] = 0ull;
    float c = 0.f, h = 0.f;

    const ulonglong2* xgp = (const ulonglong2*)(g_xg + (size_t)b * POOL_T * 128);
    ulonglong2 pre[4];
    #pragma unroll
    for (int u = 0; u < 4; u++) pre[u] = xgp[u * 32 + j];
    __syncwarp();

    for (int t = 0; t < POOL_T; t += 4) {
        #pragma unroll
        for (int u = 0; u < 4; u++) {       /* u static -> pre[u] in regs */
            int tt = t + u;
            ulonglong2 z4 = pre[u];
            int tn = tt + 4;
            if (tn > POOL_T - 1) tn = POOL_T - 1;
            pre[u] = xgp[(size_t)tn * 32 + j];

            const ulonglong2* hp = (const ulonglong2*)s_h2[w][tt & 1];
            u64t a0 = 0, a1 = 0, a2 = 0, a3 = 0;
            u64t d0 = 0, d1 = 0, d2 = 0, d3 = 0;
            #pragma unroll
            for (int kq = 0; kq < 8; kq++) {
                ulonglong2 h2 = hp[kq];
                ffma2(a0, w2[0][2 * kq], h2.x);
                ffma2(a1, w2[1][2 * kq], h2.x);
                ffma2(a2, w2[2][2 * kq], h2.x);
                ffma2(a3, w2[3][2 * kq], h2.x);
                ffma2(d0, w2[0][2 * kq + 1], h2.y);
                ffma2(d1, w2[1][2 * kq + 1], h2.y);
                ffma2(d2, w2[2][2 * kq + 1], h2.y);
                ffma2(d3, w2[3][2 * kq + 1], h2.y);
            }
            fadd2(a0, d0); fadd2(a1, d1); fadd2(a2, d2); fadd2(a3, d3);

            float xi, xf, xg2, xo, lo, hi;
            upk2(z4.x, xi, xf);
            upk2(z4.y, xg2, xo);
            upk2(a0, lo, hi); float zi = xi  + lo + hi;
            upk2(a1, lo, hi); float zf = xf  + lo + hi;
            upk2(a2, lo, hi); float zg = xg2 + lo + hi;
            upk2(a3, lo, hi); float zo = xo  + lo + hi;

            float ai = sig_p(zi), af = sig_p(zf);
            float ag = tanh_p(zg), ao = sig_p(zo);
            c = fmaf(af, c, ai * ag);
            h = ao * tanh_p(c * TL2E);

            float hn = __shfl_down_sync(0xffffffffu, h, 1);
            if (!(j & 1)) s_h2[w][(tt & 1) ^ 1][j >> 1] = pk2(h, hn);
            __syncwarp();
        }
    }

    float v = fc_w[j] * h;
    #pragma unroll
    for (int off = 16; off; off >>= 1)
        v += __shfl_down_sync(0xffffffffu, v, off);
    if (j == 0) out[b] = v + fc_b[0];
}

/* ======================================================================== */
extern "C" void kernel_launch(void* const* d_in, const int* in_sizes, int n_in,
                              void* d_out, int out_size)
{
    const float* x      = (const float*)d_in[0];
    const float* conv_w = (const float*)d_in[1];
    const float* conv_b = (const float*)d_in[2];
    const float* w_ih   = (const float*)d_in[3];
    const float* w_hh   = (const float*)d_in[4];
    const float* b_ih   = (const float*)d_in[5];
    const float* b_hh   = (const float*)d_in[6];
    const float* fc_w   = (const float*)d_in[7];
    const float* fc_b   = (const float*)d_in[8];
    float* out = (float*)d_out;

    precompute_kernel<<<1, 256>>>(conv_w);
    feat_kernel<<<B_SZ * 8, 128>>>(x);

    size_t smem_c = (size_t)NCH * ROWP2 * 8 + (size_t)NCH * 32 * 24;
    cudaFuncSetAttribute(conv_pool2_kernel,
                         cudaFuncAttributeMaxDynamicSharedMemorySize, (int)smem_c);
    conv_pool2_kernel<<<B_SZ * 4, 512, smem_c>>>(conv_b);

    size_t smem_g = (size_t)(64 * 66) * sizeof(u64t) +
                    (size_t)(64 * 132) * sizeof(float);
    cudaFuncSetAttribute(xg2_kernel,
                         cudaFuncAttributeMaxDynamicSharedMemorySize, (int)smem_g);
    xg2_kernel<<<(B_SZ * POOL_T) / XGT, 256, smem_g>>>(w_ih, b_ih, b_hh);

    lstm4_kernel<<<B_SZ / 8, 256>>>(w_hh, fc_w, fc_b, out);
}

// round 5
// speedup vs baseline: 1.3828x; 1.1730x over previous
#include <cuda_runtime.h>
#include <math.h>

#define B_SZ     256
#define S_LEN    1024
#define T_LEN    21
#define NFREQ    11
#define NCH      32
#define COUT     64
#define POOL_T   512
#define HID      32
#define NWROWS   46
#define ROWP2    264     /* conv smem row pitch in u64 */
#define XGT      128     /* rows per CTA in xg GEMM */

#define L2E   1.4426950408889634f
#define TL2E  2.8853900817779268f

typedef unsigned long long u64t;

/* ---------------- device scratch (module-static, no runtime alloc) ------ */
__device__ __align__(16) float g_tw[T_LEN * NFREQ * 2];
__device__ __align__(16) float g_L[NWROWS * T_LEN];
__device__ __align__(16) ulonglong2 g_w01[NCH * 32];
__device__ __align__(16) u64t g_w2v[NCH * 32];
__device__ __align__(16) float g_feat[B_SZ * NCH * S_LEN];
__device__ __align__(16) float g_pooled[B_SZ * POOL_T * COUT];
__device__ __align__(16) float g_xg[B_SZ * POOL_T * 128];

__constant__ float c_lo[8] = {
    -0.010597401784997278f,  0.032883011666982945f,  0.030841381835986965f,
    -0.18703481171888114f,  -0.02798376941698385f,   0.6308807679295904f,
     0.7148465705525415f,    0.23037781330885523f };
__constant__ float c_hi[8] = {
    -0.23037781330885523f,   0.7148465705525415f,   -0.6308807679295904f,
    -0.02798376941698385f,   0.18703481171888114f,   0.030841381835986965f,
    -0.032883011666982945f, -0.010597401784997278f };

/* ---------------- packed f32x2 + fast-math helpers ---------------------- */
static __device__ __forceinline__ u64t pk2(float a, float b) {
    u64t r;
    asm("mov.b64 %0,{%1,%2};" : "=l"(r) : "f"(a), "f"(b));
    return r;
}
static __device__ __forceinline__ void upk2(u64t v, float& a, float& b) {
    asm("mov.b64 {%0,%1},%2;" : "=f"(a), "=f"(b) : "l"(v));
}
static __device__ __forceinline__ void ffma2(u64t& d, u64t a, u64t b) {
    asm("fma.rn.f32x2 %0,%1,%2,%0;" : "+l"(d) : "l"(a), "l"(b));
}
static __device__ __forceinline__ void fadd2(u64t& d, u64t a) {
    asm("add.rn.f32x2 %0,%0,%1;" : "+l"(d) : "l"(a));
}
static __device__ __forceinline__ float ex2f(float x) {
    float r; asm("ex2.approx.f32 %0,%1;" : "=f"(r) : "f"(x)); return r;
}
static __device__ __forceinline__ float rcpf(float x) {
    float r; asm("rcp.approx.f32 %0,%1;" : "=f"(r) : "f"(x)); return r;
}
static __device__ __forceinline__ float sig_p(float zp) {   /* z pre-scaled L2E  */
    return rcpf(1.f + ex2f(-zp));
}
static __device__ __forceinline__ float tanh_p(float zp) {  /* z pre-scaled 2L2E */
    return fmaf(2.f, rcpf(1.f + ex2f(-zp)), -1.f);
}

/* ============ K0: twiddles, wavelet map L, paired conv weights =========== */
__global__ void precompute_kernel(const float* __restrict__ conv_w)
{
    int tid = threadIdx.x;

    for (int i = tid; i < T_LEN * NFREQ; i += blockDim.x) {
        int n = i / NFREQ, k = i % NFREQ;
        double ang = 2.0 * (double)(k * n) / 21.0;
        g_tw[2 * i]     = (float)cospi(ang);
        g_tw[2 * i + 1] = (float)(-sinpi(ang));
    }

    if (tid < T_LEN) {
        float a[21];
        #pragma unroll
        for (int i = 0; i < 21; i++) a[i] = (i == tid) ? 1.f : 0.f;
        int n = 21;
        const int rowbase[4] = {32, 22, 14, 7};
        for (int lev = 0; lev < 4; lev++) {
            int mout = (n + 5) / 2 + 1;
            float cA[14];
            for (int m = 0; m < mout; m++) {
                float aL = 0.f, aH = 0.f;
                #pragma unroll
                for (int j = 0; j < 8; j++) {
                    int idx = 2 * m + 1 - j;
                    if (idx < 0)  idx = -idx - 1;
                    if (idx >= n) idx = 2 * n - 1 - idx;
                    aL += c_lo[j] * a[idx];
                    aH += c_hi[j] * a[idx];
                }
                cA[m] = aL;
                g_L[(rowbase[lev] + m) * T_LEN + tid] = aH;
            }
            for (int m = 0; m < mout; m++) a[m] = cA[m];
            n = mout;
        }
        for (int m = 0; m < n; m++)
            g_L[m * T_LEN + tid] = a[m];
    }
    __syncthreads();

    for (int idx = tid; idx < NCH * 32; idx += blockDim.x) {
        int ci = idx >> 5, cp = idx & 31;
        float vlo[3], vhi[3];
        #pragma unroll
        for (int k = 0; k < 3; k++) {
            float a = conv_w[(cp * 78 + ci) * 3 + k];
            float b = conv_w[((cp + 32) * 78 + ci) * 3 + k];
            if (ci < T_LEN) {
                for (int j = 0; j < NWROWS; j++) {
                    float l = g_L[j * T_LEN + ci];
                    a += conv_w[(cp * 78 + 32 + j) * 3 + k] * l;
                    b += conv_w[((cp + 32) * 78 + 32 + j) * 3 + k] * l;
                }
            }
            vlo[k] = a; vhi[k] = b;
        }
        ulonglong2 w01;
        w01.x = pk2(vlo[0], vhi[0]);
        w01.y = pk2(vlo[1], vhi[1]);
        g_w01[idx] = w01;
        g_w2v[idx] = pk2(vlo[2], vhi[2]);
    }
}

/* ============ K1: feat[b][ch][s] = [x(21), |rfft|(11)] =================== */
__global__ void __launch_bounds__(128) feat_kernel(const float* __restrict__ x)
{
    __shared__ float sx[128 * T_LEN];
    __shared__ float stw[T_LEN * NFREQ * 2];

    int b  = blockIdx.x >> 3;
    int s0 = (blockIdx.x & 7) << 7;
    int tid = threadIdx.x;

    for (int i = tid; i < 128 * T_LEN; i += 128)
        sx[i] = x[(size_t)(b * S_LEN + s0) * T_LEN + i];
    for (int i = tid; i < T_LEN * NFREQ * 2; i += 128)
        stw[i] = g_tw[i];
    __syncthreads();

    float xr[T_LEN];
    #pragma unroll
    for (int i = 0; i < T_LEN; i++) xr[i] = sx[tid * T_LEN + i];

    int s = s0 + tid;
    float* fb = g_feat + (size_t)b * NCH * S_LEN + s;
    #pragma unroll
    for (int i = 0; i < T_LEN; i++) fb[i * S_LEN] = xr[i];

    for (int k = 0; k < NFREQ; k++) {
        float re = 0.f, im = 0.f;
        #pragma unroll
        for (int n = 0; n < T_LEN; n++) {
            float cw = stw[(n * NFREQ + k) * 2];
            float sw = stw[(n * NFREQ + k) * 2 + 1];
            re = fmaf(xr[n], cw, re);
            im = fmaf(xr[n], sw, im);
        }
        fb[(T_LEN + k) * S_LEN] = sqrtf(re * re + im * im);
    }
}

/* ============ K2: conv3 + ReLU + maxpool2, FFMA2 channel pairs =========== */
__global__ void __launch_bounds__(512) conv_pool2_kernel(const float* __restrict__ conv_b)
{
    extern __shared__ u64t sm2[];
    u64t*       sdup = sm2;
    ulonglong2* sw01 = (ulonglong2*)(sm2 + NCH * ROWP2);
    u64t*       sw2v = (u64t*)(sw01 + NCH * 32);

    int tid = threadIdx.x;
    int b   = blockIdx.x >> 2;
    int s0  = (blockIdx.x & 3) * 256;
    int cp  = tid & 31;
    int sg  = tid >> 5;
    int cs  = sg * 16;

    const float* fb = g_feat + (size_t)b * NCH * S_LEN;
    for (int i = tid; i < NCH * 258; i += 512) {
        int ci = i / 258, col = i % 258;
        int s = s0 + col - 1;
        float v = (s >= 0 && s < S_LEN) ? fb[ci * S_LEN + s] : 0.f;
        sdup[ci * ROWP2 + col] = pk2(v, v);
    }
    for (int i = tid; i < NCH * 32; i += 512) {
        sw01[i] = g_w01[i];
        sw2v[i] = g_w2v[i];
    }
    __syncthreads();

    u64t bias2 = pk2(conv_b[cp], conv_b[cp + 32]);
    u64t acc[16];
    #pragma unroll
    for (int i = 0; i < 16; i++) acc[i] = bias2;

    for (int ci = 0; ci < NCH; ci++) {
        const ulonglong2* vp = (const ulonglong2*)(sdup + ci * ROWP2 + cs);
        ulonglong2 w01 = sw01[ci * 32 + cp];
        u64t       wk2 = sw2v[ci * 32 + cp];
        u64t v[18];
        #pragma unroll
        for (int q = 0; q < 9; q++) {
            ulonglong2 t2 = vp[q];
            v[2 * q] = t2.x; v[2 * q + 1] = t2.y;
        }
        #pragma unroll
        for (int i = 0; i < 16; i++) {
            ffma2(acc[i], w01.x, v[i]);
            ffma2(acc[i], w01.y, v[i + 1]);
            ffma2(acc[i], wk2,   v[i + 2]);
        }
    }

    float* pout = g_pooled + (size_t)b * POOL_T * COUT;
    int t0 = (s0 + cs) >> 1;
    #pragma unroll
    for (int i = 0; i < 8; i++) {
        float l0, h0, l1, h1;
        upk2(acc[2 * i],     l0, h0);
        upk2(acc[2 * i + 1], l1, h1);
        pout[(t0 + i) * COUT + cp]      = fmaxf(fmaxf(l0, l1), 0.f);
        pout[(t0 + i) * COUT + cp + 32] = fmaxf(fmaxf(h0, h1), 0.f);
    }
}

/* ============ K2b: xg = pooled @ Wcol + bias, gate-prescaled ============= */
__global__ void __launch_bounds__(256) xg2_kernel(
    const float* __restrict__ w_ih, const float* __restrict__ b_ih,
    const float* __restrict__ b_hh)
{
    extern __shared__ u64t smw[];
    u64t*  sW = smw;
    float* sA = (float*)(smw + 64 * 66);

    int tid = threadIdx.x;
    size_t R0 = (size_t)blockIdx.x * XGT;

    for (int idx = tid; idx < 64 * 64; idx += 256) {
        int k = idx >> 6, cp = idx & 63;
        int j = cp >> 1, g0 = (cp & 1) * 2;
        float s0f = (cp & 1) ? TL2E : L2E;
        sW[k * 66 + cp] = pk2(w_ih[(g0 * 32 + j) * 64 + k] * s0f,
                              w_ih[((g0 + 1) * 32 + j) * 64 + k] * L2E);
    }

    const float* Ap = g_pooled + R0 * 64;
    for (int idx = tid; idx < XGT * 16; idx += 256) {
        int r = idx >> 4, q = idx & 15;
        float4 v = *(const float4*)(Ap + r * 64 + q * 4);
        sA[(4 * q + 0) * 132 + r] = v.x;
        sA[(4 * q + 1) * 132 + r] = v.y;
        sA[(4 * q + 2) * 132 + r] = v.z;
        sA[(4 * q + 3) * 132 + r] = v.w;
    }
    __syncthreads();

    int tx = tid & 15, ty = tid >> 4;
    int r0 = ty * 8;

    u64t acc[8][4];
    #pragma unroll
    for (int i = 0; i < 8; i++)
        #pragma unroll
        for (int q = 0; q < 4; q++) acc[i][q] = 0ull;

    #pragma unroll 4
    for (int k = 0; k < 64; k++) {
        const float* ar = sA + k * 132 + r0;
        float4 av0 = *(const float4*)ar;
        float4 av1 = *(const float4*)(ar + 4);
        u64t ad[8] = { pk2(av0.x, av0.x), pk2(av0.y, av0.y),
                       pk2(av0.z, av0.z), pk2(av0.w, av0.w),
                       pk2(av1.x, av1.x), pk2(av1.y, av1.y),
                       pk2(av1.z, av1.z), pk2(av1.w, av1.w) };
        const u64t* wr = sW + k * 66 + tx;
        u64t wv[4] = { wr[0], wr[16], wr[32], wr[48] };
        #pragma unroll
        for (int i = 0; i < 8; i++)
            #pragma unroll
            for (int q = 0; q < 4; q++)
                ffma2(acc[i][q], ad[i], wv[q]);
    }

    float* outp = g_xg + R0 * 128;
    #pragma unroll
    for (int q = 0; q < 4; q++) {
        int cp = tx + q * 16;
        int j = cp >> 1, g0 = (cp & 1) * 2;
        int gi0 = g0 * 32 + j, gi1 = (g0 + 1) * 32 + j;
        float s0f = (cp & 1) ? TL2E : L2E;
        u64t bp = pk2((b_ih[gi0] + b_hh[gi0]) * s0f,
                      (b_ih[gi1] + b_hh[gi1]) * L2E);
        #pragma unroll
        for (int i = 0; i < 8; i++) {
            u64t s = acc[i][q];
            fadd2(s, bp);
            float lo, hi;
            upk2(s, lo, hi);
            *(float2*)(outp + (size_t)(r0 + i) * 128 + cp * 2) = make_float2(lo, hi);
        }
    }
}

/* ============ K3: LSTM v5 — 2 warps/CTA, grid 128, min-chain ============= */
__global__ void __launch_bounds__(64) lstm5_kernel(
    const float* __restrict__ w_hh, const float* __restrict__ fc_w,
    const float* __restrict__ fc_b, float* __restrict__ out)
{
    __shared__ __align__(16) float s_h[2][2][32];   /* [warp][buf][j] */

    int w = threadIdx.x >> 5;
    int j = threadIdx.x & 31;
    int b = blockIdx.x * 2 + w;

    const float sc[4] = { L2E, L2E, TL2E, L2E };
    u64t w2[4][16];
    #pragma unroll
    for (int g = 0; g < 4; g++) {
        const float4* row = (const float4*)(w_hh + (g * 32 + j) * 32);
        #pragma unroll
        for (int q = 0; q < 8; q++) {
            float4 v = row[q];
            w2[g][2 * q]     = pk2(v.x * sc[g], v.y * sc[g]);
            w2[g][2 * q + 1] = pk2(v.z * sc[g], v.w * sc[g]);
        }
    }

    s_h[w][0][j] = 0.f;
    float c = 0.f, h = 0.f;

    const ulonglong2* xgp = (const ulonglong2*)(g_xg + (size_t)b * POOL_T * 128);
    ulonglong2 pre[4];
    #pragma unroll
    for (int u = 0; u < 4; u++) pre[u] = xgp[u * 32 + j];
    __syncwarp();

    for (int t = 0; t < POOL_T; t += 4) {
        #pragma unroll
        for (int u = 0; u < 4; u++) {
            int tt = t + u;
            ulonglong2 z4 = pre[u];
            int tn = tt + 4;
            if (tn > POOL_T - 1) tn = POOL_T - 1;
            pre[u] = xgp[(size_t)tn * 32 + j];

            const ulonglong2* hp = (const ulonglong2*)s_h[w][tt & 1];

            /* init accumulators straight from prefetched xg (masked) */
            u64t a0 = z4.x & 0xffffffffull, a1 = z4.x >> 32;
            u64t a2 = z4.y & 0xffffffffull, a3 = z4.y >> 32;
            u64t b0 = 0, b1 = 0, b2 = 0, b3 = 0;   /* even-k, 2nd half */
            u64t d0 = 0, d1 = 0, d2 = 0, d3 = 0;   /* odd-k,  1st half */
            u64t e0 = 0, e1 = 0, e2 = 0, e3 = 0;   /* odd-k,  2nd half */

            #pragma unroll
            for (int kq = 0; kq < 4; kq++) {
                ulonglong2 h2 = hp[kq];
                ffma2(a0, w2[0][2 * kq], h2.x);
                ffma2(a1, w2[1][2 * kq], h2.x);
                ffma2(a2, w2[2][2 * kq], h2.x);
                ffma2(a3, w2[3][2 * kq], h2.x);
                ffma2(d0, w2[0][2 * kq + 1], h2.y);
                ffma2(d1, w2[1][2 * kq + 1], h2.y);
                ffma2(d2, w2[2][2 * kq + 1], h2.y);
                ffma2(d3, w2[3][2 * kq + 1], h2.y);
            }
            #pragma unroll
            for (int kq = 4; kq < 8; kq++) {
                ulonglong2 h2 = hp[kq];
                ffma2(b0, w2[0][2 * kq], h2.x);
                ffma2(b1, w2[1][2 * kq], h2.x);
                ffma2(b2, w2[2][2 * kq], h2.x);
                ffma2(b3, w2[3][2 * kq], h2.x);
                ffma2(e0, w2[0][2 * kq + 1], h2.y);
                ffma2(e1, w2[1][2 * kq + 1], h2.y);
                ffma2(e2, w2[2][2 * kq + 1], h2.y);
                ffma2(e3, w2[3][2 * kq + 1], h2.y);
            }
            fadd2(a0, b0); fadd2(d0, e0); fadd2(a0, d0);
            fadd2(a1, b1); fadd2(d1, e1); fadd2(a1, d1);
            fadd2(a2, b2); fadd2(d2, e2); fadd2(a2, d2);
            fadd2(a3, b3); fadd2(d3, e3); fadd2(a3, d3);

            float lo, hi;
            upk2(a0, lo, hi); float zi = lo + hi;
            upk2(a1, lo, hi); float zf = lo + hi;
            upk2(a2, lo, hi); float zg = lo + hi;
            upk2(a3, lo, hi); float zo = lo + hi;

            float ai = sig_p(zi), af = sig_p(zf);
            float ag = tanh_p(zg), ao = sig_p(zo);
            c = fmaf(af, c, ai * ag);
            h = ao * tanh_p(c * TL2E);

            s_h[w][(tt & 1) ^ 1][j] = h;
            __syncwarp();
        }
    }

    float v = fc_w[j] * h;
    #pragma unroll
    for (int off = 16; off; off >>= 1)
        v += __shfl_down_sync(0xffffffffu, v, off);
    if (j == 0) out[b] = v + fc_b[0];
}

/* ======================================================================== */
extern "C" void kernel_launch(void* const* d_in, const int* in_sizes, int n_in,
                              void* d_out, int out_size)
{
    const float* x      = (const float*)d_in[0];
    const float* conv_w = (const float*)d_in[1];
    const float* conv_b = (const float*)d_in[2];
    const float* w_ih   = (const float*)d_in[3];
    const float* w_hh   = (const float*)d_in[4];
    const float* b_ih   = (const float*)d_in[5];
    const float* b_hh   = (const float*)d_in[6];
    const float* fc_w   = (const float*)d_in[7];
    const float* fc_b   = (const float*)d_in[8];
    float* out = (float*)d_out;

    precompute_kernel<<<1, 256>>>(conv_w);
    feat_kernel<<<B_SZ * 8, 128>>>(x);

    size_t smem_c = (size_t)NCH * ROWP2 * 8 + (size_t)NCH * 32 * 24;
    cudaFuncSetAttribute(conv_pool2_kernel,
                         cudaFuncAttributeMaxDynamicSharedMemorySize, (int)smem_c);
    conv_pool2_kernel<<<B_SZ * 4, 512, smem_c>>>(conv_b);

    size_t smem_g = (size_t)(64 * 66) * sizeof(u64t) +
                    (size_t)(64 * 132) * sizeof(float);
    cudaFuncSetAttribute(xg2_kernel,
                         cudaFuncAttributeMaxDynamicSharedMemorySize, (int)smem_g);
    xg2_kernel<<<(B_SZ * POOL_T) / XGT, 256, smem_g>>>(w_ih, b_ih, b_hh);

    lstm5_kernel<<<B_SZ / 2, 64>>>(w_hh, fc_w, fc_b, out);
}